// round 13
// baseline (speedup 1.0000x reference)
#include <cuda_runtime.h>
#include <cuda_fp16.h>
#include <cstdint>

#define S_LEN 2048
#define DM    2048
#define NH    16
#define DK    128
#define NB    4

// -------- scratch (static __device__ arrays) --------
__device__ __half g_Q[(size_t)NB * NH * S_LEN * DK];    // [b,h,s,dk] fp16
__device__ __half g_K[(size_t)NB * NH * S_LEN * DK];
__device__ __half g_V[(size_t)NB * NH * S_LEN * DK];
__device__ __half g_Attn[(size_t)NB * S_LEN * DM];      // [b,s,h*DK+v] fp16
__device__ __half g_xh[(size_t)NB * S_LEN * DM];        // x fp16
__device__ __half g_Wh[4][(size_t)DM * DM];             // weights fp16

// -------- helpers --------
__device__ __forceinline__ void mma_f16(float c[4], const uint32_t a[4], const uint32_t b[2]) {
    asm volatile(
        "mma.sync.aligned.m16n8k16.row.col.f32.f16.f16.f32 "
        "{%0,%1,%2,%3}, {%4,%5,%6,%7}, {%8,%9}, {%0,%1,%2,%3};"
        : "+f"(c[0]), "+f"(c[1]), "+f"(c[2]), "+f"(c[3])
        : "r"(a[0]), "r"(a[1]), "r"(a[2]), "r"(a[3]), "r"(b[0]), "r"(b[1]));
}

__device__ __forceinline__ void ldsm4(uint32_t& r0, uint32_t& r1, uint32_t& r2, uint32_t& r3,
                                      const void* p) {
    uint32_t a = (uint32_t)__cvta_generic_to_shared(p);
    asm volatile("ldmatrix.sync.aligned.m8n8.x4.shared.b16 {%0,%1,%2,%3}, [%4];"
                 : "=r"(r0), "=r"(r1), "=r"(r2), "=r"(r3) : "r"(a));
}
__device__ __forceinline__ void ldsm4t(uint32_t& r0, uint32_t& r1, uint32_t& r2, uint32_t& r3,
                                       const void* p) {
    uint32_t a = (uint32_t)__cvta_generic_to_shared(p);
    asm volatile("ldmatrix.sync.aligned.m8n8.x4.trans.shared.b16 {%0,%1,%2,%3}, [%4];"
                 : "=r"(r0), "=r"(r1), "=r"(r2), "=r"(r3) : "r"(a));
}

__device__ __forceinline__ void cp16(void* sptr, const void* g) {
    uint32_t sa = (uint32_t)__cvta_generic_to_shared(sptr);
    asm volatile("cp.async.cg.shared.global [%0], [%1], 16;" :: "r"(sa), "l"(g));
}
__device__ __forceinline__ void cp_commit() { asm volatile("cp.async.commit_group;"); }
template <int N>
__device__ __forceinline__ void cp_wait() { asm volatile("cp.async.wait_group %0;" :: "n"(N)); }

__device__ __forceinline__ float fex2(float x) {
    float r;
    asm("ex2.approx.ftz.f32 %0, %1;" : "=f"(r) : "f"(x));
    return r;
}

// ============================================================================
// fused f32 -> f16 conversion: grid.y picks a slice (0-3: quarters of x, 4-7: weights)
// ============================================================================
__global__ void cvt_all(const float* __restrict__ x,
                        const float* __restrict__ w0, const float* __restrict__ w1,
                        const float* __restrict__ w2, const float* __restrict__ w3,
                        __half* __restrict__ xh, __half* __restrict__ wh) {
    const int seg = blockIdx.y;
    const size_t WSZ = (size_t)DM * DM;
    const size_t n4 = WSZ / 4;
    const float* in;
    __half* out;
    if (seg < 4)      { in = x + seg * WSZ;  out = xh + seg * WSZ; }
    else if (seg == 4){ in = w0;             out = wh + 0 * WSZ; }
    else if (seg == 5){ in = w1;             out = wh + 1 * WSZ; }
    else if (seg == 6){ in = w2;             out = wh + 2 * WSZ; }
    else              { in = w3;             out = wh + 3 * WSZ; }

    size_t i = blockIdx.x * blockDim.x + threadIdx.x;
    size_t st = (size_t)gridDim.x * blockDim.x;
    for (; i < n4; i += st) {
        float4 v = ((const float4*)in)[i];
        __half2 h0 = __floats2half2_rn(v.x, v.y);
        __half2 h1 = __floats2half2_rn(v.z, v.w);
        uint2 u;
        u.x = *(uint32_t*)&h0; u.y = *(uint32_t*)&h1;
        ((uint2*)out)[i] = u;
    }
}

// ============================================================================
// NT GEMM (fp16 in, fp32 acc): C[8192,2048] = A[8192,2048] * W[2048,2048]^T
// R9 proven config: tile 128x128, 256 thr (8 warps 4x2), warp 32x64, BK=64,
// 3-stage cp.async with prefetch interleaved into the MMA loop, 2 CTAs/SM.
// MODE 1: gridDim.z=3 -> QKV, scatter half [b,h,s,dk].  MODE 0: float out.
// ============================================================================
#define BK     64
#define APITCH 72                  // halfs per row (64 + 8 pad = 144B)
#define STG    3
#define T_ST   (128 * APITCH)      // halfs per stage per tensor
#define GEMM_SMEM (STG * T_ST * 2 * 2)   // 110592 bytes

template <int MODE>
__global__ __launch_bounds__(256, 2) void gemm_nt(const __half* __restrict__ A,
                                                  const __half* __restrict__ Wb,
                                                  void* C0, void* C1, void* C2) {
    extern __shared__ __half sm[];
    __half* As = sm;                 // [STG][128][APITCH]
    __half* Bs = sm + STG * T_ST;    // [STG][128][APITCH]

    const int z = blockIdx.z;
    const __half* Bw = (MODE == 1) ? Wb + (size_t)z * DM * DM : Wb;
    void* Cv = (MODE == 1) ? (z == 0 ? C0 : (z == 1 ? C1 : C2)) : C0;

    const int m0 = blockIdx.y * 128;
    const int n0 = blockIdx.x * 128;
    const int tid = threadIdx.x;
    const int warp = tid >> 5, lane = tid & 31;
    const int wm = warp >> 1, wn = warp & 1;     // 4 x 2 warps
    const int la3 = lane & 3, lg = lane >> 2;

    float acc[2][8][4];
#pragma unroll
    for (int i = 0; i < 2; i++)
#pragma unroll
        for (int j = 0; j < 8; j++)
#pragma unroll
            for (int e = 0; e < 4; e++) acc[i][j][e] = 0.f;

    const int ldr = tid >> 3;            // 0..31
    const int ldc = (tid & 7) * 8;       // half col

    auto loadStage = [&](int s, int k0) {
        __half* as = As + s * T_ST;
        __half* bs = Bs + s * T_ST;
#pragma unroll
        for (int p = 0; p < 4; p++) {
            int r = ldr + p * 32;
            cp16(as + r * APITCH + ldc, &A[(size_t)(m0 + r) * 2048 + k0 + ldc]);
            cp16(bs + r * APITCH + ldc, &Bw[(size_t)(n0 + r) * 2048 + k0 + ldc]);
        }
        cp_commit();
    };

    loadStage(0, 0);
    loadStage(1, BK);

    const int a_row = lane & 15, a_col = (lane >> 4) * 8;
    const int b_row = (lane & 7) + ((lane >> 4) & 1) * 8;
    const int b_col = ((lane >> 3) & 1) * 8;

    const int NCH = 2048 / BK;    // 32
    int s = 0;
    int sl = 2;
    for (int ch = 0; ch < NCH; ch++) {
        if (ch < NCH - 1) cp_wait<1>(); else cp_wait<0>();
        __syncthreads();

        const bool pf = (ch <= NCH - 3);
        const int k0p = (ch + 2) * BK;
        __half* asl = As + sl * T_ST;
        __half* bsl = Bs + sl * T_ST;

        const __half* as = As + s * T_ST;
        const __half* bs = Bs + s * T_ST;
#pragma unroll
        for (int kk = 0; kk < 4; kk++) {
            if (pf) {
                int r = ldr + kk * 32;
                cp16(asl + r * APITCH + ldc, &A[(size_t)(m0 + r) * 2048 + k0p + ldc]);
                cp16(bsl + r * APITCH + ldc, &Bw[(size_t)(n0 + r) * 2048 + k0p + ldc]);
            }
            uint32_t af[2][4], bf[8][2];
#pragma unroll
            for (int mf = 0; mf < 2; mf++)
                ldsm4(af[mf][0], af[mf][1], af[mf][2], af[mf][3],
                      as + (wm * 32 + mf * 16 + a_row) * APITCH + kk * 16 + a_col);
#pragma unroll
            for (int j = 0; j < 4; j++) {
                uint32_t r0, r1, r2, r3;
                ldsm4(r0, r1, r2, r3,
                      bs + (wn * 64 + j * 16 + b_row) * APITCH + kk * 16 + b_col);
                bf[2 * j][0] = r0; bf[2 * j][1] = r1;
                bf[2 * j + 1][0] = r2; bf[2 * j + 1][1] = r3;
            }
#pragma unroll
            for (int mf = 0; mf < 2; mf++)
#pragma unroll
                for (int nf = 0; nf < 8; nf++) mma_f16(acc[mf][nf], af[mf], bf[nf]);
        }
        cp_commit();
        if (pf) { if (++sl == STG) sl = 0; }
        if (++s == STG) s = 0;
    }

#pragma unroll
    for (int mf = 0; mf < 2; mf++)
#pragma unroll
        for (int nf = 0; nf < 8; nf++)
#pragma unroll
            for (int ep = 0; ep < 2; ep++) {
                int r = m0 + wm * 32 + mf * 16 + lg + ep * 8;
                int c = n0 + wn * 64 + nf * 8 + la3 * 2;
                float v0 = acc[mf][nf][2 * ep], v1 = acc[mf][nf][2 * ep + 1];
                if (MODE == 0) {
                    float2 f2 = make_float2(v0, v1);
                    *(float2*)&((float*)Cv)[(size_t)r * 2048 + c] = f2;
                } else {
                    int b = r >> 11, sq = r & 2047;
                    int h = c >> 7, d = c & 127;
                    __half2 h2 = __floats2half2_rn(v0, v1);
                    *(__half2*)&((__half*)Cv)[((((size_t)b * NH) + h) * S_LEN + sq) * DK + d] = h2;
                }
            }
}

// ============================================================================
// Flash attention (causal, fp16).
// NEW (R13): CTA = 64 q-rows, 128 thr (4 warps x 16 q-rows), BK=128 K-tiles,
// SINGLE-buffered K/V smem (69.6KB) -> 2 CTAs/SM with natural registers.
// Cross-CTA overlap replaces in-CTA double buffering.  Q in regs, P in regs,
// exp2-domain softmax, heavy q-blocks first.
// ============================================================================
#define KPITCH 136                  // halfs (128 + 8 pad = 272B)
#define KTILE  (128 * KPITCH)       // halfs per tensor tile
#define FLASH_SMEM (2 * KTILE * 2)  // K+V single stage = 69632 bytes

__global__ __launch_bounds__(128) void flash_attn() {
    extern __shared__ __half sm[];
    __half* Ks = sm;                // [128][KPITCH]
    __half* Vs = sm + KTILE;

    const int bh = blockIdx.y;
    const int qblk = gridDim.x - 1 - blockIdx.x;     // heavy-first (0..31)
    const int q0 = qblk * 64;
    const __half* Qg = g_Q + (size_t)bh * S_LEN * DK;
    const __half* Kg = g_K + (size_t)bh * S_LEN * DK;
    const __half* Vg = g_V + (size_t)bh * S_LEN * DK;

    const int tid = threadIdx.x;
    const int warp = tid >> 5, lane = tid & 31;
    const int la3 = lane & 3, lg = lane >> 2;

    // ---- Q fragments (16 rows per warp) straight into registers ----
    uint32_t qf[8][4];
    {
        const __half* Q0 = Qg + (size_t)(q0 + warp * 16 + lg) * DK + la3 * 2;
#pragma unroll
        for (int kk = 0; kk < 8; kk++) {
            qf[kk][0] = *(const uint32_t*)&Q0[kk * 16];
            qf[kk][1] = *(const uint32_t*)&Q0[8 * DK + kk * 16];
            qf[kk][2] = *(const uint32_t*)&Q0[kk * 16 + 8];
            qf[kk][3] = *(const uint32_t*)&Q0[8 * DK + kk * 16 + 8];
        }
    }

    float m_prev0 = -1e30f, m_prev1 = -1e30f;
    float l0 = 0.f, l1 = 0.f;
    float o[16][4];
#pragma unroll
    for (int nf = 0; nf < 16; nf++)
#pragma unroll
        for (int e = 0; e < 4; e++) o[nf][e] = 0.f;

    const int qrow0 = q0 + warp * 16 + lg;
    const int nkt = (qblk >> 1) + 1;     // 128-wide K tiles (causal, 64-q CTA)
    const float sc2 = 0.12751743f;       // log2(e)/sqrt(128)

    const int b_row = (lane & 7) + ((lane >> 4) & 1) * 8;
    const int b_col = ((lane >> 3) & 1) * 8;
    const int v_row = lane & 15;
    const int v_col = (lane >> 4) * 8;

    for (int kt = 0; kt < nkt; kt++) {
        const int k0 = kt * 128;

        // ---- load K/V tile (single buffer; sibling CTA hides this phase) ----
        // 128 rows x 16 chunks x 2 tensors = 4096 cp16 ; 32 per thread
#pragma unroll
        for (int p = 0; p < 16; p++) {
            int i = tid + p * 128;
            int r = i >> 4, c8 = (i & 15) * 8;
            cp16(Ks + r * KPITCH + c8, &Kg[(size_t)(k0 + r) * DK + c8]);
            cp16(Vs + r * KPITCH + c8, &Vg[(size_t)(k0 + r) * DK + c8]);
        }
        cp_commit();
        cp_wait<0>();
        __syncthreads();               // tile data visible to all warps

        const bool diag = (kt == nkt - 1);

        // ---- S = Q K^T  (16 q x 128 k per warp) ----
        float s[16][4];
#pragma unroll
        for (int nf = 0; nf < 16; nf++)
#pragma unroll
            for (int e = 0; e < 4; e++) s[nf][e] = 0.f;

#pragma unroll
        for (int kk = 0; kk < 8; kk++) {
            uint32_t bf[16][2];
#pragma unroll
            for (int j = 0; j < 8; j++) {
                uint32_t r0, r1, r2, r3;
                ldsm4(r0, r1, r2, r3,
                      Ks + (j * 16 + b_row) * KPITCH + kk * 16 + b_col);
                bf[2 * j][0] = r0; bf[2 * j][1] = r1;
                bf[2 * j + 1][0] = r2; bf[2 * j + 1][1] = r3;
            }
#pragma unroll
            for (int nf = 0; nf < 16; nf++) mma_f16(s[nf], qf[kk], bf[nf]);
        }

        // ---- scale (+ causal mask on diagonal tile) + row max ----
        float mx0 = -1e30f, mx1 = -1e30f;
        if (diag) {
#pragma unroll
            for (int nf = 0; nf < 16; nf++)
#pragma unroll
                for (int e = 0; e < 4; e++) {
                    int col = k0 + nf * 8 + la3 * 2 + (e & 1);
                    int qr  = qrow0 + ((e >= 2) ? 8 : 0);
                    float v = s[nf][e] * sc2;
                    if (col > qr) v = -1e30f;
                    s[nf][e] = v;
                    if (e < 2) { mx0 = fmaxf(mx0, v); } else { mx1 = fmaxf(mx1, v); }
                }
        } else {
#pragma unroll
            for (int nf = 0; nf < 16; nf++)
#pragma unroll
                for (int e = 0; e < 4; e++) {
                    float v = s[nf][e] * sc2;
                    s[nf][e] = v;
                    if (e < 2) { mx0 = fmaxf(mx0, v); } else { mx1 = fmaxf(mx1, v); }
                }
        }
        mx0 = fmaxf(mx0, __shfl_xor_sync(0xffffffff, mx0, 1));
        mx0 = fmaxf(mx0, __shfl_xor_sync(0xffffffff, mx0, 2));
        mx1 = fmaxf(mx1, __shfl_xor_sync(0xffffffff, mx1, 1));
        mx1 = fmaxf(mx1, __shfl_xor_sync(0xffffffff, mx1, 2));

        float mn0 = (kt == 0) ? mx0 : fmaxf(m_prev0, mx0);
        float mn1 = (kt == 0) ? mx1 : fmaxf(m_prev1, mx1);

        float sum0 = 0.f, sum1 = 0.f;
#pragma unroll
        for (int nf = 0; nf < 16; nf++)
#pragma unroll
            for (int e = 0; e < 4; e++) {
                float p = fex2(s[nf][e] - ((e < 2) ? mn0 : mn1));
                s[nf][e] = p;
                if (e < 2) sum0 += p; else sum1 += p;
            }
        sum0 += __shfl_xor_sync(0xffffffff, sum0, 1);
        sum0 += __shfl_xor_sync(0xffffffff, sum0, 2);
        sum1 += __shfl_xor_sync(0xffffffff, sum1, 1);
        sum1 += __shfl_xor_sync(0xffffffff, sum1, 2);

        if (kt == 0) {
            l0 = sum0;
            l1 = sum1;
        } else {
            float corr0 = fex2(m_prev0 - mn0);
            float corr1 = fex2(m_prev1 - mn1);
            l0 = l0 * corr0 + sum0;
            l1 = l1 * corr1 + sum1;
#pragma unroll
            for (int nf = 0; nf < 16; nf++) {
                o[nf][0] *= corr0; o[nf][1] *= corr0;
                o[nf][2] *= corr1; o[nf][3] *= corr1;
            }
        }
        m_prev0 = mn0; m_prev1 = mn1;

        // ---- pack P fragments (16 q x 128 k -> 8 A-frags) ----
        uint32_t ph[8][4];
#pragma unroll
        for (int kk2 = 0; kk2 < 8; kk2++) {
            __half2 h;
            h = __floats2half2_rn(s[2 * kk2][0], s[2 * kk2][1]);         ph[kk2][0] = *(uint32_t*)&h;
            h = __floats2half2_rn(s[2 * kk2][2], s[2 * kk2][3]);         ph[kk2][1] = *(uint32_t*)&h;
            h = __floats2half2_rn(s[2 * kk2 + 1][0], s[2 * kk2 + 1][1]); ph[kk2][2] = *(uint32_t*)&h;
            h = __floats2half2_rn(s[2 * kk2 + 1][2], s[2 * kk2 + 1][3]); ph[kk2][3] = *(uint32_t*)&h;
        }

        // ---- O += P V  (16 q x 128 v, k-depth 128) ----
#pragma unroll
        for (int kk2 = 0; kk2 < 8; kk2++) {
#pragma unroll
            for (int j = 0; j < 8; j++) {
                uint32_t r0, r1, r2, r3;
                ldsm4t(r0, r1, r2, r3,
                       Vs + (kk2 * 16 + v_row) * KPITCH + j * 16 + v_col);
                uint32_t bf0[2] = {r0, r1};
                uint32_t bf1[2] = {r2, r3};
                mma_f16(o[2 * j], ph[kk2], bf0);
                mma_f16(o[2 * j + 1], ph[kk2], bf1);
            }
        }
        __syncthreads();               // compute done before next tile's loads
    }

    const int b = bh >> 4, h = bh & 15;
    float inv0 = 1.f / l0, inv1 = 1.f / l1;
#pragma unroll
    for (int nf = 0; nf < 16; nf++)
#pragma unroll
        for (int ep = 0; ep < 2; ep++) {
            int q = qrow0 + ep * 8;
            int v = nf * 8 + la3 * 2;
            float inv = ep ? inv1 : inv0;
            __half2 h2 = __floats2half2_rn(o[nf][2 * ep] * inv, o[nf][2 * ep + 1] * inv);
            *(__half2*)&g_Attn[((size_t)b * S_LEN + q) * DM + h * DK + v] = h2;
        }
}

// ============================================================================
// launch
// ============================================================================
extern "C" void kernel_launch(void* const* d_in, const int* in_sizes, int n_in,
                              void* d_out, int out_size) {
    const float* x  = (const float*)d_in[0];
    const float* WQ = (const float*)d_in[1];
    const float* WK = (const float*)d_in[2];
    const float* WV = (const float*)d_in[3];
    const float* WO = (const float*)d_in[4];
    float* out = (float*)d_out;

    __half *pQ, *pK, *pV, *pA, *pXh, *pWh;
    cudaGetSymbolAddress((void**)&pQ,  g_Q);
    cudaGetSymbolAddress((void**)&pK,  g_K);
    cudaGetSymbolAddress((void**)&pV,  g_V);
    cudaGetSymbolAddress((void**)&pA,  g_Attn);
    cudaGetSymbolAddress((void**)&pXh, g_xh);
    cudaGetSymbolAddress((void**)&pWh, g_Wh);

    const size_t WSZ = (size_t)DM * DM;
    cudaFuncSetAttribute(gemm_nt<0>, cudaFuncAttributeMaxDynamicSharedMemorySize, GEMM_SMEM);
    cudaFuncSetAttribute(gemm_nt<1>, cudaFuncAttributeMaxDynamicSharedMemorySize, GEMM_SMEM);
    cudaFuncSetAttribute(flash_attn, cudaFuncAttributeMaxDynamicSharedMemorySize, FLASH_SMEM);

    cvt_all<<<dim3(96, 8), 256>>>(x, WQ, WK, WV, WO, pXh, pWh);

    dim3 qkv_grid(16, 64, 3);   // N/128, M/128, {Q,K,V}
    gemm_nt<1><<<qkv_grid, 256, GEMM_SMEM>>>(pXh, pWh, pQ, pK, pV);

    dim3 fgrid(32, 64);         // S/64 q-blocks, B*H
    flash_attn<<<fgrid, 128, FLASH_SMEM>>>();

    dim3 o_grid(16, 64, 1);
    gemm_nt<0><<<o_grid, 256, GEMM_SMEM>>>(pA, pWh + 3 * WSZ, out, nullptr, nullptr);
}

// round 14
// speedup vs baseline: 1.0396x; 1.0396x over previous
#include <cuda_runtime.h>
#include <cuda_fp16.h>
#include <cstdint>

#define S_LEN 2048
#define DM    2048
#define NH    16
#define DK    128
#define NB    4

// -------- scratch (static __device__ arrays) --------
__device__ __half g_Q[(size_t)NB * NH * S_LEN * DK];    // [b,h,s,dk] fp16
__device__ __half g_K[(size_t)NB * NH * S_LEN * DK];
__device__ __half g_V[(size_t)NB * NH * S_LEN * DK];
__device__ __half g_Attn[(size_t)NB * S_LEN * DM];      // [b,s,h*DK+v] fp16
__device__ __half g_xh[(size_t)NB * S_LEN * DM];        // x fp16
__device__ __half g_Wh[4][(size_t)DM * DM];             // weights fp16

// -------- helpers --------
__device__ __forceinline__ void mma_f16(float c[4], const uint32_t a[4], const uint32_t b[2]) {
    asm volatile(
        "mma.sync.aligned.m16n8k16.row.col.f32.f16.f16.f32 "
        "{%0,%1,%2,%3}, {%4,%5,%6,%7}, {%8,%9}, {%0,%1,%2,%3};"
        : "+f"(c[0]), "+f"(c[1]), "+f"(c[2]), "+f"(c[3])
        : "r"(a[0]), "r"(a[1]), "r"(a[2]), "r"(a[3]), "r"(b[0]), "r"(b[1]));
}

__device__ __forceinline__ void ldsm4(uint32_t& r0, uint32_t& r1, uint32_t& r2, uint32_t& r3,
                                      const void* p) {
    uint32_t a = (uint32_t)__cvta_generic_to_shared(p);
    asm volatile("ldmatrix.sync.aligned.m8n8.x4.shared.b16 {%0,%1,%2,%3}, [%4];"
                 : "=r"(r0), "=r"(r1), "=r"(r2), "=r"(r3) : "r"(a));
}
__device__ __forceinline__ void ldsm4t(uint32_t& r0, uint32_t& r1, uint32_t& r2, uint32_t& r3,
                                       const void* p) {
    uint32_t a = (uint32_t)__cvta_generic_to_shared(p);
    asm volatile("ldmatrix.sync.aligned.m8n8.x4.trans.shared.b16 {%0,%1,%2,%3}, [%4];"
                 : "=r"(r0), "=r"(r1), "=r"(r2), "=r"(r3) : "r"(a));
}

__device__ __forceinline__ void cp16(void* sptr, const void* g) {
    uint32_t sa = (uint32_t)__cvta_generic_to_shared(sptr);
    asm volatile("cp.async.cg.shared.global [%0], [%1], 16;" :: "r"(sa), "l"(g));
}
__device__ __forceinline__ void cp_commit() { asm volatile("cp.async.commit_group;"); }
template <int N>
__device__ __forceinline__ void cp_wait() { asm volatile("cp.async.wait_group %0;" :: "n"(N)); }

__device__ __forceinline__ float fex2(float x) {
    float r;
    asm("ex2.approx.ftz.f32 %0, %1;" : "=f"(r) : "f"(x));
    return r;
}

// ============================================================================
// fused f32 -> f16 conversion: grid.y picks a slice (0-3: quarters of x, 4-7: weights)
// ============================================================================
__global__ void cvt_all(const float* __restrict__ x,
                        const float* __restrict__ w0, const float* __restrict__ w1,
                        const float* __restrict__ w2, const float* __restrict__ w3,
                        __half* __restrict__ xh, __half* __restrict__ wh) {
    const int seg = blockIdx.y;
    const size_t WSZ = (size_t)DM * DM;
    const size_t n4 = WSZ / 4;
    const float* in;
    __half* out;
    if (seg < 4)      { in = x + seg * WSZ;  out = xh + seg * WSZ; }
    else if (seg == 4){ in = w0;             out = wh + 0 * WSZ; }
    else if (seg == 5){ in = w1;             out = wh + 1 * WSZ; }
    else if (seg == 6){ in = w2;             out = wh + 2 * WSZ; }
    else              { in = w3;             out = wh + 3 * WSZ; }

    size_t i = blockIdx.x * blockDim.x + threadIdx.x;
    size_t st = (size_t)gridDim.x * blockDim.x;
    for (; i < n4; i += st) {
        float4 v = ((const float4*)in)[i];
        __half2 h0 = __floats2half2_rn(v.x, v.y);
        __half2 h1 = __floats2half2_rn(v.z, v.w);
        uint2 u;
        u.x = *(uint32_t*)&h0; u.y = *(uint32_t*)&h1;
        ((uint2*)out)[i] = u;
    }
}

// ============================================================================
// NT GEMM (fp16 in, fp32 acc): C[8192,2048] = A[8192,2048] * W[2048,2048]^T
// R9 proven config: tile 128x128, 256 thr (8 warps 4x2), warp 32x64, BK=64,
// 3-stage cp.async with prefetch interleaved into the MMA loop, 2 CTAs/SM.
// MODE 1: gridDim.z=3 -> QKV, scatter half [b,h,s,dk].  MODE 0: float out.
// ============================================================================
#define BK     64
#define APITCH 72                  // halfs per row (64 + 8 pad = 144B)
#define STG    3
#define T_ST   (128 * APITCH)      // halfs per stage per tensor
#define GEMM_SMEM (STG * T_ST * 2 * 2)   // 110592 bytes

template <int MODE>
__global__ __launch_bounds__(256, 2) void gemm_nt(const __half* __restrict__ A,
                                                  const __half* __restrict__ Wb,
                                                  void* C0, void* C1, void* C2) {
    extern __shared__ __half sm[];
    __half* As = sm;                 // [STG][128][APITCH]
    __half* Bs = sm + STG * T_ST;    // [STG][128][APITCH]

    const int z = blockIdx.z;
    const __half* Bw = (MODE == 1) ? Wb + (size_t)z * DM * DM : Wb;
    void* Cv = (MODE == 1) ? (z == 0 ? C0 : (z == 1 ? C1 : C2)) : C0;

    const int m0 = blockIdx.y * 128;
    const int n0 = blockIdx.x * 128;
    const int tid = threadIdx.x;
    const int warp = tid >> 5, lane = tid & 31;
    const int wm = warp >> 1, wn = warp & 1;     // 4 x 2 warps
    const int la3 = lane & 3, lg = lane >> 2;

    float acc[2][8][4];
#pragma unroll
    for (int i = 0; i < 2; i++)
#pragma unroll
        for (int j = 0; j < 8; j++)
#pragma unroll
            for (int e = 0; e < 4; e++) acc[i][j][e] = 0.f;

    const int ldr = tid >> 3;            // 0..31
    const int ldc = (tid & 7) * 8;       // half col

    auto loadStage = [&](int s, int k0) {
        __half* as = As + s * T_ST;
        __half* bs = Bs + s * T_ST;
#pragma unroll
        for (int p = 0; p < 4; p++) {
            int r = ldr + p * 32;
            cp16(as + r * APITCH + ldc, &A[(size_t)(m0 + r) * 2048 + k0 + ldc]);
            cp16(bs + r * APITCH + ldc, &Bw[(size_t)(n0 + r) * 2048 + k0 + ldc]);
        }
        cp_commit();
    };

    loadStage(0, 0);
    loadStage(1, BK);

    const int a_row = lane & 15, a_col = (lane >> 4) * 8;
    const int b_row = (lane & 7) + ((lane >> 4) & 1) * 8;
    const int b_col = ((lane >> 3) & 1) * 8;

    const int NCH = 2048 / BK;    // 32
    int s = 0;
    int sl = 2;
    for (int ch = 0; ch < NCH; ch++) {
        if (ch < NCH - 1) cp_wait<1>(); else cp_wait<0>();
        __syncthreads();

        const bool pf = (ch <= NCH - 3);
        const int k0p = (ch + 2) * BK;
        __half* asl = As + sl * T_ST;
        __half* bsl = Bs + sl * T_ST;

        const __half* as = As + s * T_ST;
        const __half* bs = Bs + s * T_ST;
#pragma unroll
        for (int kk = 0; kk < 4; kk++) {
            if (pf) {
                int r = ldr + kk * 32;
                cp16(asl + r * APITCH + ldc, &A[(size_t)(m0 + r) * 2048 + k0p + ldc]);
                cp16(bsl + r * APITCH + ldc, &Bw[(size_t)(n0 + r) * 2048 + k0p + ldc]);
            }
            uint32_t af[2][4], bf[8][2];
#pragma unroll
            for (int mf = 0; mf < 2; mf++)
                ldsm4(af[mf][0], af[mf][1], af[mf][2], af[mf][3],
                      as + (wm * 32 + mf * 16 + a_row) * APITCH + kk * 16 + a_col);
#pragma unroll
            for (int j = 0; j < 4; j++) {
                uint32_t r0, r1, r2, r3;
                ldsm4(r0, r1, r2, r3,
                      bs + (wn * 64 + j * 16 + b_row) * APITCH + kk * 16 + b_col);
                bf[2 * j][0] = r0; bf[2 * j][1] = r1;
                bf[2 * j + 1][0] = r2; bf[2 * j + 1][1] = r3;
            }
#pragma unroll
            for (int mf = 0; mf < 2; mf++)
#pragma unroll
                for (int nf = 0; nf < 8; nf++) mma_f16(acc[mf][nf], af[mf], bf[nf]);
        }
        cp_commit();
        if (pf) { if (++sl == STG) sl = 0; }
        if (++s == STG) s = 0;
    }

#pragma unroll
    for (int mf = 0; mf < 2; mf++)
#pragma unroll
        for (int nf = 0; nf < 8; nf++)
#pragma unroll
            for (int ep = 0; ep < 2; ep++) {
                int r = m0 + wm * 32 + mf * 16 + lg + ep * 8;
                int c = n0 + wn * 64 + nf * 8 + la3 * 2;
                float v0 = acc[mf][nf][2 * ep], v1 = acc[mf][nf][2 * ep + 1];
                if (MODE == 0) {
                    float2 f2 = make_float2(v0, v1);
                    *(float2*)&((float*)Cv)[(size_t)r * 2048 + c] = f2;
                } else {
                    int b = r >> 11, sq = r & 2047;
                    int h = c >> 7, d = c & 127;
                    __half2 h2 = __floats2half2_rn(v0, v1);
                    *(__half2*)&((__half*)Cv)[((((size_t)b * NH) + h) * S_LEN + sq) * DK + d] = h2;
                }
            }
}

// ============================================================================
// Flash attention (causal, fp16).  R12 geometry: block = 128 q-rows of one
// (b,h), 256 thr (8 warps x 16 q-rows), BK=128 K-tiles, double-buffered K/V,
// Q in regs, P in regs, exp2-domain softmax, heavy q-blocks first.
// NEW (R14): next-tile cp.async burst issued BETWEEN the QK MMA loop and the
// softmax (LSU idle during softmax -> no MIO collision with LDSM), and ONE
// __syncthreads per tile (top barrier also guards the stage overwrite).
// ============================================================================
#define KPITCH 136                 // halfs (128 + 8 pad = 272B)
#define KST    (128 * KPITCH)      // one stage (128 rows)
#define FLASH_SMEM (4 * KST * 2)   // 139264 bytes

__global__ __launch_bounds__(256, 1) void flash_attn() {
    extern __shared__ __half sm[];
    __half* Ks = sm;               // [2][128][KPITCH]
    __half* Vs = sm + 2 * KST;

    const int bh = blockIdx.y;
    const int qblk = gridDim.x - 1 - blockIdx.x;     // heavy-first
    const int q0 = qblk * 128;
    const __half* Qg = g_Q + (size_t)bh * S_LEN * DK;
    const __half* Kg = g_K + (size_t)bh * S_LEN * DK;
    const __half* Vg = g_V + (size_t)bh * S_LEN * DK;

    const int tid = threadIdx.x;
    const int warp = tid >> 5, lane = tid & 31;
    const int la3 = lane & 3, lg = lane >> 2;

    uint32_t qf[8][4];
    {
        const __half* Q0 = Qg + (size_t)(q0 + warp * 16 + lg) * DK + la3 * 2;
#pragma unroll
        for (int kk = 0; kk < 8; kk++) {
            qf[kk][0] = *(const uint32_t*)&Q0[kk * 16];
            qf[kk][1] = *(const uint32_t*)&Q0[8 * DK + kk * 16];
            qf[kk][2] = *(const uint32_t*)&Q0[kk * 16 + 8];
            qf[kk][3] = *(const uint32_t*)&Q0[8 * DK + kk * 16 + 8];
        }
    }

    auto loadKV = [&](int s, int k0) {
        __half* ks = Ks + s * KST;
        __half* vs = Vs + s * KST;
        // 128 rows x 16 chunks(8 halfs) = 2048 per tensor ; 8 per thread each
#pragma unroll
        for (int p = 0; p < 8; p++) {
            int i = tid + p * 256;
            int r = i >> 4, c8 = (i & 15) * 8;
            cp16(ks + r * KPITCH + c8, &Kg[(size_t)(k0 + r) * DK + c8]);
            cp16(vs + r * KPITCH + c8, &Vg[(size_t)(k0 + r) * DK + c8]);
        }
        cp_commit();
    };

    float m_prev0 = -1e30f, m_prev1 = -1e30f;
    float l0 = 0.f, l1 = 0.f;
    float o[16][4];
#pragma unroll
    for (int nf = 0; nf < 16; nf++)
#pragma unroll
        for (int e = 0; e < 4; e++) o[nf][e] = 0.f;

    const int qrow0 = q0 + warp * 16 + lg;
    const int nkt = qblk + 1;          // 128-wide K tiles (causal)
    const float sc2 = 0.12751743f;     // log2(e)/sqrt(128)

    const int b_row = (lane & 7) + ((lane >> 4) & 1) * 8;
    const int b_col = ((lane >> 3) & 1) * 8;
    const int v_row = lane & 15;
    const int v_col = (lane >> 4) * 8;

    loadKV(0, 0);

    for (int kt = 0; kt < nkt; kt++) {
        const int k0 = kt * 128;
        cp_wait<0>();                  // only in-flight group = this tile's data
        __syncthreads();               // data ready; also guards stage overwrite

        const int st = kt & 1;
        const __half* ks = Ks + st * KST;
        const __half* vs = Vs + st * KST;
        const bool diag = (kt == nkt - 1);

        // ---- S = Q K^T  (16 q x 128 k per warp) ----
        float s[16][4];
#pragma unroll
        for (int nf = 0; nf < 16; nf++)
#pragma unroll
            for (int e = 0; e < 4; e++) s[nf][e] = 0.f;

#pragma unroll
        for (int kk = 0; kk < 8; kk++) {
            uint32_t bf[16][2];
#pragma unroll
            for (int j = 0; j < 8; j++) {
                uint32_t r0, r1, r2, r3;
                ldsm4(r0, r1, r2, r3,
                      ks + (j * 16 + b_row) * KPITCH + kk * 16 + b_col);
                bf[2 * j][0] = r0; bf[2 * j][1] = r1;
                bf[2 * j + 1][0] = r2; bf[2 * j + 1][1] = r3;
            }
#pragma unroll
            for (int nf = 0; nf < 16; nf++) mma_f16(s[nf], qf[kk], bf[nf]);
        }

        // ---- issue next tile's loads here: overlaps softmax (no LSU use) ----
        if (kt + 1 < nkt) loadKV((kt + 1) & 1, (kt + 1) * 128);

        // ---- scale (+ causal mask on diagonal tile) + row max ----
        float mx0 = -1e30f, mx1 = -1e30f;
        if (diag) {
#pragma unroll
            for (int nf = 0; nf < 16; nf++)
#pragma unroll
                for (int e = 0; e < 4; e++) {
                    int col = k0 + nf * 8 + la3 * 2 + (e & 1);
                    int qr  = qrow0 + ((e >= 2) ? 8 : 0);
                    float v = s[nf][e] * sc2;
                    if (col > qr) v = -1e30f;
                    s[nf][e] = v;
                    if (e < 2) { mx0 = fmaxf(mx0, v); } else { mx1 = fmaxf(mx1, v); }
                }
        } else {
#pragma unroll
            for (int nf = 0; nf < 16; nf++)
#pragma unroll
                for (int e = 0; e < 4; e++) {
                    float v = s[nf][e] * sc2;
                    s[nf][e] = v;
                    if (e < 2) { mx0 = fmaxf(mx0, v); } else { mx1 = fmaxf(mx1, v); }
                }
        }
        mx0 = fmaxf(mx0, __shfl_xor_sync(0xffffffff, mx0, 1));
        mx0 = fmaxf(mx0, __shfl_xor_sync(0xffffffff, mx0, 2));
        mx1 = fmaxf(mx1, __shfl_xor_sync(0xffffffff, mx1, 1));
        mx1 = fmaxf(mx1, __shfl_xor_sync(0xffffffff, mx1, 2));

        float mn0 = (kt == 0) ? mx0 : fmaxf(m_prev0, mx0);
        float mn1 = (kt == 0) ? mx1 : fmaxf(m_prev1, mx1);

        float sum0 = 0.f, sum1 = 0.f;
#pragma unroll
        for (int nf = 0; nf < 16; nf++)
#pragma unroll
            for (int e = 0; e < 4; e++) {
                float p = fex2(s[nf][e] - ((e < 2) ? mn0 : mn1));
                s[nf][e] = p;
                if (e < 2) sum0 += p; else sum1 += p;
            }
        sum0 += __shfl_xor_sync(0xffffffff, sum0, 1);
        sum0 += __shfl_xor_sync(0xffffffff, sum0, 2);
        sum1 += __shfl_xor_sync(0xffffffff, sum1, 1);
        sum1 += __shfl_xor_sync(0xffffffff, sum1, 2);

        if (kt == 0) {
            l0 = sum0;
            l1 = sum1;
        } else {
            float corr0 = fex2(m_prev0 - mn0);
            float corr1 = fex2(m_prev1 - mn1);
            l0 = l0 * corr0 + sum0;
            l1 = l1 * corr1 + sum1;
#pragma unroll
            for (int nf = 0; nf < 16; nf++) {
                o[nf][0] *= corr0; o[nf][1] *= corr0;
                o[nf][2] *= corr1; o[nf][3] *= corr1;
            }
        }
        m_prev0 = mn0; m_prev1 = mn1;

        // ---- pack P fragments (16 q x 128 k -> 8 A-frags) ----
        uint32_t ph[8][4];
#pragma unroll
        for (int kk2 = 0; kk2 < 8; kk2++) {
            __half2 h;
            h = __floats2half2_rn(s[2 * kk2][0], s[2 * kk2][1]);         ph[kk2][0] = *(uint32_t*)&h;
            h = __floats2half2_rn(s[2 * kk2][2], s[2 * kk2][3]);         ph[kk2][1] = *(uint32_t*)&h;
            h = __floats2half2_rn(s[2 * kk2 + 1][0], s[2 * kk2 + 1][1]); ph[kk2][2] = *(uint32_t*)&h;
            h = __floats2half2_rn(s[2 * kk2 + 1][2], s[2 * kk2 + 1][3]); ph[kk2][3] = *(uint32_t*)&h;
        }

        // ---- O += P V  (16 q x 128 v, k-depth 128) ----
#pragma unroll
        for (int kk2 = 0; kk2 < 8; kk2++) {
#pragma unroll
            for (int j = 0; j < 8; j++) {
                uint32_t r0, r1, r2, r3;
                ldsm4t(r0, r1, r2, r3,
                       vs + (kk2 * 16 + v_row) * KPITCH + j * 16 + v_col);
                uint32_t bf0[2] = {r0, r1};
                uint32_t bf1[2] = {r2, r3};
                mma_f16(o[2 * j], ph[kk2], bf0);
                mma_f16(o[2 * j + 1], ph[kk2], bf1);
            }
        }
        // no end-of-tile sync: next top barrier guards the stage overwrite
    }

    const int b = bh >> 4, h = bh & 15;
    float inv0 = 1.f / l0, inv1 = 1.f / l1;
#pragma unroll
    for (int nf = 0; nf < 16; nf++)
#pragma unroll
        for (int ep = 0; ep < 2; ep++) {
            int q = qrow0 + ep * 8;
            int v = nf * 8 + la3 * 2;
            float inv = ep ? inv1 : inv0;
            __half2 h2 = __floats2half2_rn(o[nf][2 * ep] * inv, o[nf][2 * ep + 1] * inv);
            *(__half2*)&g_Attn[((size_t)b * S_LEN + q) * DM + h * DK + v] = h2;
        }
}

// ============================================================================
// launch
// ============================================================================
extern "C" void kernel_launch(void* const* d_in, const int* in_sizes, int n_in,
                              void* d_out, int out_size) {
    const float* x  = (const float*)d_in[0];
    const float* WQ = (const float*)d_in[1];
    const float* WK = (const float*)d_in[2];
    const float* WV = (const float*)d_in[3];
    const float* WO = (const float*)d_in[4];
    float* out = (float*)d_out;

    __half *pQ, *pK, *pV, *pA, *pXh, *pWh;
    cudaGetSymbolAddress((void**)&pQ,  g_Q);
    cudaGetSymbolAddress((void**)&pK,  g_K);
    cudaGetSymbolAddress((void**)&pV,  g_V);
    cudaGetSymbolAddress((void**)&pA,  g_Attn);
    cudaGetSymbolAddress((void**)&pXh, g_xh);
    cudaGetSymbolAddress((void**)&pWh, g_Wh);

    const size_t WSZ = (size_t)DM * DM;
    cudaFuncSetAttribute(gemm_nt<0>, cudaFuncAttributeMaxDynamicSharedMemorySize, GEMM_SMEM);
    cudaFuncSetAttribute(gemm_nt<1>, cudaFuncAttributeMaxDynamicSharedMemorySize, GEMM_SMEM);
    cudaFuncSetAttribute(flash_attn, cudaFuncAttributeMaxDynamicSharedMemorySize, FLASH_SMEM);

    cvt_all<<<dim3(96, 8), 256>>>(x, WQ, WK, WV, WO, pXh, pWh);

    dim3 qkv_grid(16, 64, 3);   // N/128, M/128, {Q,K,V}
    gemm_nt<1><<<qkv_grid, 256, GEMM_SMEM>>>(pXh, pWh, pQ, pK, pV);

    dim3 fgrid(16, 64);         // S/128 q-blocks, B*H
    flash_attn<<<fgrid, 256, FLASH_SMEM>>>();

    dim3 o_grid(16, 64, 1);
    gemm_nt<0><<<o_grid, 256, GEMM_SMEM>>>(pA, pWh + 3 * WSZ, out, nullptr, nullptr);
}

// round 16
// speedup vs baseline: 1.0412x; 1.0016x over previous
#include <cuda_runtime.h>
#include <cuda_fp16.h>
#include <cstdint>

#define S_LEN 2048
#define DM    2048
#define NH    16
#define DK    128
#define NB    4

// -------- scratch (static __device__ arrays) --------
__device__ __half g_Q[(size_t)NB * NH * S_LEN * DK];    // [b,h,s,dk] fp16
__device__ __half g_K[(size_t)NB * NH * S_LEN * DK];
__device__ __half g_V[(size_t)NB * NH * S_LEN * DK];
__device__ __half g_Attn[(size_t)NB * S_LEN * DM];      // [b,s,h*DK+v] fp16
__device__ __half g_xh[(size_t)NB * S_LEN * DM];        // x fp16
__device__ __half g_Wh[4][(size_t)DM * DM];             // weights fp16

// -------- helpers --------
__device__ __forceinline__ void mma_f16(float c[4], const uint32_t a[4], const uint32_t b[2]) {
    asm volatile(
        "mma.sync.aligned.m16n8k16.row.col.f32.f16.f16.f32 "
        "{%0,%1,%2,%3}, {%4,%5,%6,%7}, {%8,%9}, {%0,%1,%2,%3};"
        : "+f"(c[0]), "+f"(c[1]), "+f"(c[2]), "+f"(c[3])
        : "r"(a[0]), "r"(a[1]), "r"(a[2]), "r"(a[3]), "r"(b[0]), "r"(b[1]));
}

__device__ __forceinline__ void ldsm4(uint32_t& r0, uint32_t& r1, uint32_t& r2, uint32_t& r3,
                                      const void* p) {
    uint32_t a = (uint32_t)__cvta_generic_to_shared(p);
    asm volatile("ldmatrix.sync.aligned.m8n8.x4.shared.b16 {%0,%1,%2,%3}, [%4];"
                 : "=r"(r0), "=r"(r1), "=r"(r2), "=r"(r3) : "r"(a));
}
__device__ __forceinline__ void ldsm4t(uint32_t& r0, uint32_t& r1, uint32_t& r2, uint32_t& r3,
                                       const void* p) {
    uint32_t a = (uint32_t)__cvta_generic_to_shared(p);
    asm volatile("ldmatrix.sync.aligned.m8n8.x4.trans.shared.b16 {%0,%1,%2,%3}, [%4];"
                 : "=r"(r0), "=r"(r1), "=r"(r2), "=r"(r3) : "r"(a));
}

__device__ __forceinline__ void cp16(void* sptr, const void* g) {
    uint32_t sa = (uint32_t)__cvta_generic_to_shared(sptr);
    asm volatile("cp.async.cg.shared.global [%0], [%1], 16;" :: "r"(sa), "l"(g));
}
__device__ __forceinline__ void cp_commit() { asm volatile("cp.async.commit_group;"); }
template <int N>
__device__ __forceinline__ void cp_wait() { asm volatile("cp.async.wait_group %0;" :: "n"(N)); }

__device__ __forceinline__ float fex2(float x) {
    float r;
    asm("ex2.approx.ftz.f32 %0, %1;" : "=f"(r) : "f"(x));
    return r;
}

// ============================================================================
// fused f32 -> f16 conversion; 2-way independent unroll for MLP=2.
// grid.y picks a slice (0-3: quarters of x, 4-7: weights)
// ============================================================================
__global__ void cvt_all(const float* __restrict__ x,
                        const float* __restrict__ w0, const float* __restrict__ w1,
                        const float* __restrict__ w2, const float* __restrict__ w3,
                        __half* __restrict__ xh, __half* __restrict__ wh) {
    const int seg = blockIdx.y;
    const size_t WSZ = (size_t)DM * DM;
    const size_t n4 = WSZ / 4;
    const float* in;
    __half* out;
    if (seg < 4)      { in = x + seg * WSZ;  out = xh + seg * WSZ; }
    else if (seg == 4){ in = w0;             out = wh + 0 * WSZ; }
    else if (seg == 5){ in = w1;             out = wh + 1 * WSZ; }
    else if (seg == 6){ in = w2;             out = wh + 2 * WSZ; }
    else              { in = w3;             out = wh + 3 * WSZ; }

    size_t i = blockIdx.x * blockDim.x + threadIdx.x;
    const size_t st = (size_t)gridDim.x * blockDim.x;
    for (; i + st < n4; i += 2 * st) {
        float4 v0 = ((const float4*)in)[i];
        float4 v1 = ((const float4*)in)[i + st];
        __half2 a0 = __floats2half2_rn(v0.x, v0.y);
        __half2 a1 = __floats2half2_rn(v0.z, v0.w);
        __half2 b0 = __floats2half2_rn(v1.x, v1.y);
        __half2 b1 = __floats2half2_rn(v1.z, v1.w);
        uint2 u0, u1;
        u0.x = *(uint32_t*)&a0; u0.y = *(uint32_t*)&a1;
        u1.x = *(uint32_t*)&b0; u1.y = *(uint32_t*)&b1;
        ((uint2*)out)[i] = u0;
        ((uint2*)out)[i + st] = u1;
    }
    if (i < n4) {
        float4 v = ((const float4*)in)[i];
        __half2 h0 = __floats2half2_rn(v.x, v.y);
        __half2 h1 = __floats2half2_rn(v.z, v.w);
        uint2 u;
        u.x = *(uint32_t*)&h0; u.y = *(uint32_t*)&h1;
        ((uint2*)out)[i] = u;
    }
}

// ============================================================================
// NT GEMM (fp16 in, fp32 acc): C[8192,2048] = A[8192,2048] * W[2048,2048]^T
// R9 proven config: tile 128x128, 256 thr (8 warps 4x2), warp 32x64, BK=64,
// 3-stage cp.async with prefetch interleaved into the MMA loop, 2 CTAs/SM.
// MODE 1: gridDim.z=3 -> QKV, scatter half [b,h,s,dk].  MODE 0: float out.
// ============================================================================
#define BK     64
#define APITCH 72                  // halfs per row (64 + 8 pad = 144B)
#define STG    3
#define T_ST   (128 * APITCH)      // halfs per stage per tensor
#define GEMM_SMEM (STG * T_ST * 2 * 2)   // 110592 bytes

template <int MODE>
__global__ __launch_bounds__(256, 2) void gemm_nt(const __half* __restrict__ A,
                                                  const __half* __restrict__ Wb,
                                                  void* C0, void* C1, void* C2) {
    extern __shared__ __half sm[];
    __half* As = sm;                 // [STG][128][APITCH]
    __half* Bs = sm + STG * T_ST;    // [STG][128][APITCH]

    const int z = blockIdx.z;
    const __half* Bw = (MODE == 1) ? Wb + (size_t)z * DM * DM : Wb;
    void* Cv = (MODE == 1) ? (z == 0 ? C0 : (z == 1 ? C1 : C2)) : C0;

    const int m0 = blockIdx.y * 128;
    const int n0 = blockIdx.x * 128;
    const int tid = threadIdx.x;
    const int warp = tid >> 5, lane = tid & 31;
    const int wm = warp >> 1, wn = warp & 1;     // 4 x 2 warps
    const int la3 = lane & 3, lg = lane >> 2;

    float acc[2][8][4];
#pragma unroll
    for (int i = 0; i < 2; i++)
#pragma unroll
        for (int j = 0; j < 8; j++)
#pragma unroll
            for (int e = 0; e < 4; e++) acc[i][j][e] = 0.f;

    const int ldr = tid >> 3;            // 0..31
    const int ldc = (tid & 7) * 8;       // half col

    auto loadStage = [&](int s, int k0) {
        __half* as = As + s * T_ST;
        __half* bs = Bs + s * T_ST;
#pragma unroll
        for (int p = 0; p < 4; p++) {
            int r = ldr + p * 32;
            cp16(as + r * APITCH + ldc, &A[(size_t)(m0 + r) * 2048 + k0 + ldc]);
            cp16(bs + r * APITCH + ldc, &Bw[(size_t)(n0 + r) * 2048 + k0 + ldc]);
        }
        cp_commit();
    };

    loadStage(0, 0);
    loadStage(1, BK);

    const int a_row = lane & 15, a_col = (lane >> 4) * 8;
    const int b_row = (lane & 7) + ((lane >> 4) & 1) * 8;
    const int b_col = ((lane >> 3) & 1) * 8;

    const int NCH = 2048 / BK;    // 32
    int s = 0;
    int sl = 2;
    for (int ch = 0; ch < NCH; ch++) {
        if (ch < NCH - 1) cp_wait<1>(); else cp_wait<0>();
        __syncthreads();

        const bool pf = (ch <= NCH - 3);
        const int k0p = (ch + 2) * BK;
        __half* asl = As + sl * T_ST;
        __half* bsl = Bs + sl * T_ST;

        const __half* as = As + s * T_ST;
        const __half* bs = Bs + s * T_ST;
#pragma unroll
        for (int kk = 0; kk < 4; kk++) {
            if (pf) {
                int r = ldr + kk * 32;
                cp16(asl + r * APITCH + ldc, &A[(size_t)(m0 + r) * 2048 + k0p + ldc]);
                cp16(bsl + r * APITCH + ldc, &Bw[(size_t)(n0 + r) * 2048 + k0p + ldc]);
            }
            uint32_t af[2][4], bf[8][2];
#pragma unroll
            for (int mf = 0; mf < 2; mf++)
                ldsm4(af[mf][0], af[mf][1], af[mf][2], af[mf][3],
                      as + (wm * 32 + mf * 16 + a_row) * APITCH + kk * 16 + a_col);
#pragma unroll
            for (int j = 0; j < 4; j++) {
                uint32_t r0, r1, r2, r3;
                ldsm4(r0, r1, r2, r3,
                      bs + (wn * 64 + j * 16 + b_row) * APITCH + kk * 16 + b_col);
                bf[2 * j][0] = r0; bf[2 * j][1] = r1;
                bf[2 * j + 1][0] = r2; bf[2 * j + 1][1] = r3;
            }
#pragma unroll
            for (int mf = 0; mf < 2; mf++)
#pragma unroll
                for (int nf = 0; nf < 8; nf++) mma_f16(acc[mf][nf], af[mf], bf[nf]);
        }
        cp_commit();
        if (pf) { if (++sl == STG) sl = 0; }
        if (++s == STG) s = 0;
    }

#pragma unroll
    for (int mf = 0; mf < 2; mf++)
#pragma unroll
        for (int nf = 0; nf < 8; nf++)
#pragma unroll
            for (int ep = 0; ep < 2; ep++) {
                int r = m0 + wm * 32 + mf * 16 + lg + ep * 8;
                int c = n0 + wn * 64 + nf * 8 + la3 * 2;
                float v0 = acc[mf][nf][2 * ep], v1 = acc[mf][nf][2 * ep + 1];
                if (MODE == 0) {
                    float2 f2 = make_float2(v0, v1);
                    *(float2*)&((float*)Cv)[(size_t)r * 2048 + c] = f2;
                } else {
                    int b = r >> 11, sq = r & 2047;
                    int h = c >> 7, d = c & 127;
                    __half2 h2 = __floats2half2_rn(v0, v1);
                    *(__half2*)&((__half*)Cv)[((((size_t)b * NH) + h) * S_LEN + sq) * DK + d] = h2;
                }
            }
}

// ============================================================================
// Flash attention (causal, fp16).  Block = 128 q-rows of one (b,h), 256 thr
// (8 warps x 16 q-rows), BK=128 K-tiles, Q in regs, P in regs, exp2 softmax,
// loads issued in the softmax window, ONE __syncthreads per tile.
// NEW (R15): 3-stage K/V ring — loads for kt+2 issued during kt, top-of-tile
// cp_wait<1> (non-draining) instead of full drain; ~2 tiles of latency cover.
// ============================================================================
#define KPITCH 136                 // halfs (128 + 8 pad = 272B)
#define KST    (128 * KPITCH)      // one stage (128 rows)
#define FSTG   3
#define FLASH_SMEM (2 * FSTG * KST * 2)   // 208896 bytes

__global__ __launch_bounds__(256, 1) void flash_attn() {
    extern __shared__ __half sm[];
    __half* Ks = sm;               // [FSTG][128][KPITCH]
    __half* Vs = sm + FSTG * KST;

    const int bh = blockIdx.y;
    const int qblk = gridDim.x - 1 - blockIdx.x;     // heavy-first
    const int q0 = qblk * 128;
    const __half* Qg = g_Q + (size_t)bh * S_LEN * DK;
    const __half* Kg = g_K + (size_t)bh * S_LEN * DK;
    const __half* Vg = g_V + (size_t)bh * S_LEN * DK;

    const int tid = threadIdx.x;
    const int warp = tid >> 5, lane = tid & 31;
    const int la3 = lane & 3, lg = lane >> 2;

    uint32_t qf[8][4];
    {
        const __half* Q0 = Qg + (size_t)(q0 + warp * 16 + lg) * DK + la3 * 2;
#pragma unroll
        for (int kk = 0; kk < 8; kk++) {
            qf[kk][0] = *(const uint32_t*)&Q0[kk * 16];
            qf[kk][1] = *(const uint32_t*)&Q0[8 * DK + kk * 16];
            qf[kk][2] = *(const uint32_t*)&Q0[kk * 16 + 8];
            qf[kk][3] = *(const uint32_t*)&Q0[8 * DK + kk * 16 + 8];
        }
    }

    auto loadKV = [&](int s, int k0) {
        __half* ks = Ks + s * KST;
        __half* vs = Vs + s * KST;
        // 128 rows x 16 chunks(8 halfs) = 2048 per tensor ; 8 per thread each
#pragma unroll
        for (int p = 0; p < 8; p++) {
            int i = tid + p * 256;
            int r = i >> 4, c8 = (i & 15) * 8;
            cp16(ks + r * KPITCH + c8, &Kg[(size_t)(k0 + r) * DK + c8]);
            cp16(vs + r * KPITCH + c8, &Vg[(size_t)(k0 + r) * DK + c8]);
        }
        cp_commit();
    };

    float m_prev0 = -1e30f, m_prev1 = -1e30f;
    float l0 = 0.f, l1 = 0.f;
    float o[16][4];
#pragma unroll
    for (int nf = 0; nf < 16; nf++)
#pragma unroll
        for (int e = 0; e < 4; e++) o[nf][e] = 0.f;

    const int qrow0 = q0 + warp * 16 + lg;
    const int nkt = qblk + 1;          // 128-wide K tiles (causal)
    const float sc2 = 0.12751743f;     // log2(e)/sqrt(128)

    const int b_row = (lane & 7) + ((lane >> 4) & 1) * 8;
    const int b_col = ((lane >> 3) & 1) * 8;
    const int v_row = lane & 15;
    const int v_col = (lane >> 4) * 8;

    // prologue: fill 2 stages
    loadKV(0, 0);
    if (nkt > 1) loadKV(1, 128);

    int st = 0;        // stage of current tile
    int sl = 2;        // stage for tile kt+2

    for (int kt = 0; kt < nkt; kt++) {
        const int k0 = kt * 128;
        if (kt + 1 < nkt) cp_wait<1>(); else cp_wait<0>();
        __syncthreads();               // data ready; also guards stage reuse

        const __half* ks = Ks + st * KST;
        const __half* vs = Vs + st * KST;
        const bool diag = (kt == nkt - 1);

        // ---- S = Q K^T  (16 q x 128 k per warp) ----
        float s[16][4];
#pragma unroll
        for (int nf = 0; nf < 16; nf++)
#pragma unroll
            for (int e = 0; e < 4; e++) s[nf][e] = 0.f;

#pragma unroll
        for (int kk = 0; kk < 8; kk++) {
            uint32_t bf[16][2];
#pragma unroll
            for (int j = 0; j < 8; j++) {
                uint32_t r0, r1, r2, r3;
                ldsm4(r0, r1, r2, r3,
                      ks + (j * 16 + b_row) * KPITCH + kk * 16 + b_col);
                bf[2 * j][0] = r0; bf[2 * j][1] = r1;
                bf[2 * j + 1][0] = r2; bf[2 * j + 1][1] = r3;
            }
#pragma unroll
            for (int nf = 0; nf < 16; nf++) mma_f16(s[nf], qf[kk], bf[nf]);
        }

        // ---- issue tile kt+2's loads: overlaps softmax (no LSU use there) ----
        if (kt + 2 < nkt) {
            loadKV(sl, (kt + 2) * 128);
            if (++sl == FSTG) sl = 0;
        }
        if (++st == FSTG) st = 0;

        // ---- scale (+ causal mask on diagonal tile) + row max ----
        float mx0 = -1e30f, mx1 = -1e30f;
        if (diag) {
#pragma unroll
            for (int nf = 0; nf < 16; nf++)
#pragma unroll
                for (int e = 0; e < 4; e++) {
                    int col = k0 + nf * 8 + la3 * 2 + (e & 1);
                    int qr  = qrow0 + ((e >= 2) ? 8 : 0);
                    float v = s[nf][e] * sc2;
                    if (col > qr) v = -1e30f;
                    s[nf][e] = v;
                    if (e < 2) { mx0 = fmaxf(mx0, v); } else { mx1 = fmaxf(mx1, v); }
                }
        } else {
#pragma unroll
            for (int nf = 0; nf < 16; nf++)
#pragma unroll
                for (int e = 0; e < 4; e++) {
                    float v = s[nf][e] * sc2;
                    s[nf][e] = v;
                    if (e < 2) { mx0 = fmaxf(mx0, v); } else { mx1 = fmaxf(mx1, v); }
                }
        }
        mx0 = fmaxf(mx0, __shfl_xor_sync(0xffffffff, mx0, 1));
        mx0 = fmaxf(mx0, __shfl_xor_sync(0xffffffff, mx0, 2));
        mx1 = fmaxf(mx1, __shfl_xor_sync(0xffffffff, mx1, 1));
        mx1 = fmaxf(mx1, __shfl_xor_sync(0xffffffff, mx1, 2));

        float mn0 = (kt == 0) ? mx0 : fmaxf(m_prev0, mx0);
        float mn1 = (kt == 0) ? mx1 : fmaxf(m_prev1, mx1);

        float sum0 = 0.f, sum1 = 0.f;
#pragma unroll
        for (int nf = 0; nf < 16; nf++)
#pragma unroll
            for (int e = 0; e < 4; e++) {
                float p = fex2(s[nf][e] - ((e < 2) ? mn0 : mn1));
                s[nf][e] = p;
                if (e < 2) sum0 += p; else sum1 += p;
            }
        sum0 += __shfl_xor_sync(0xffffffff, sum0, 1);
        sum0 += __shfl_xor_sync(0xffffffff, sum0, 2);
        sum1 += __shfl_xor_sync(0xffffffff, sum1, 1);
        sum1 += __shfl_xor_sync(0xffffffff, sum1, 2);

        if (kt == 0) {
            l0 = sum0;
            l1 = sum1;
        } else {
            float corr0 = fex2(m_prev0 - mn0);
            float corr1 = fex2(m_prev1 - mn1);
            l0 = l0 * corr0 + sum0;
            l1 = l1 * corr1 + sum1;
#pragma unroll
            for (int nf = 0; nf < 16; nf++) {
                o[nf][0] *= corr0; o[nf][1] *= corr0;
                o[nf][2] *= corr1; o[nf][3] *= corr1;
            }
        }
        m_prev0 = mn0; m_prev1 = mn1;

        // ---- pack P fragments (16 q x 128 k -> 8 A-frags) ----
        uint32_t ph[8][4];
#pragma unroll
        for (int kk2 = 0; kk2 < 8; kk2++) {
            __half2 h;
            h = __floats2half2_rn(s[2 * kk2][0], s[2 * kk2][1]);         ph[kk2][0] = *(uint32_t*)&h;
            h = __floats2half2_rn(s[2 * kk2][2], s[2 * kk2][3]);         ph[kk2][1] = *(uint32_t*)&h;
            h = __floats2half2_rn(s[2 * kk2 + 1][0], s[2 * kk2 + 1][1]); ph[kk2][2] = *(uint32_t*)&h;
            h = __floats2half2_rn(s[2 * kk2 + 1][2], s[2 * kk2 + 1][3]); ph[kk2][3] = *(uint32_t*)&h;
        }

        // ---- O += P V  (16 q x 128 v, k-depth 128) ----
#pragma unroll
        for (int kk2 = 0; kk2 < 8; kk2++) {
#pragma unroll
            for (int j = 0; j < 8; j++) {
                uint32_t r0, r1, r2, r3;
                ldsm4t(r0, r1, r2, r3,
                       vs + (kk2 * 16 + v_row) * KPITCH + j * 16 + v_col);
                uint32_t bf0[2] = {r0, r1};
                uint32_t bf1[2] = {r2, r3};
                mma_f16(o[2 * j], ph[kk2], bf0);
                mma_f16(o[2 * j + 1], ph[kk2], bf1);
            }
        }
        // no end-of-tile sync: next top barrier guards stage reuse
    }

    const int b = bh >> 4, h = bh & 15;
    float inv0 = 1.f / l0, inv1 = 1.f / l1;
#pragma unroll
    for (int nf = 0; nf < 16; nf++)
#pragma unroll
        for (int ep = 0; ep < 2; ep++) {
            int q = qrow0 + ep * 8;
            int v = nf * 8 + la3 * 2;
            float inv = ep ? inv1 : inv0;
            __half2 h2 = __floats2half2_rn(o[nf][2 * ep] * inv, o[nf][2 * ep + 1] * inv);
            *(__half2*)&g_Attn[((size_t)b * S_LEN + q) * DM + h * DK + v] = h2;
        }
}

// ============================================================================
// launch
// ============================================================================
extern "C" void kernel_launch(void* const* d_in, const int* in_sizes, int n_in,
                              void* d_out, int out_size) {
    const float* x  = (const float*)d_in[0];
    const float* WQ = (const float*)d_in[1];
    const float* WK = (const float*)d_in[2];
    const float* WV = (const float*)d_in[3];
    const float* WO = (const float*)d_in[4];
    float* out = (float*)d_out;

    __half *pQ, *pK, *pV, *pA, *pXh, *pWh;
    cudaGetSymbolAddress((void**)&pQ,  g_Q);
    cudaGetSymbolAddress((void**)&pK,  g_K);
    cudaGetSymbolAddress((void**)&pV,  g_V);
    cudaGetSymbolAddress((void**)&pA,  g_Attn);
    cudaGetSymbolAddress((void**)&pXh, g_xh);
    cudaGetSymbolAddress((void**)&pWh, g_Wh);

    const size_t WSZ = (size_t)DM * DM;
    cudaFuncSetAttribute(gemm_nt<0>, cudaFuncAttributeMaxDynamicSharedMemorySize, GEMM_SMEM);
    cudaFuncSetAttribute(gemm_nt<1>, cudaFuncAttributeMaxDynamicSharedMemorySize, GEMM_SMEM);
    cudaFuncSetAttribute(flash_attn, cudaFuncAttributeMaxDynamicSharedMemorySize, FLASH_SMEM);

    cvt_all<<<dim3(192, 8), 256>>>(x, WQ, WK, WV, WO, pXh, pWh);

    dim3 qkv_grid(16, 64, 3);   // N/128, M/128, {Q,K,V}
    gemm_nt<1><<<qkv_grid, 256, GEMM_SMEM>>>(pXh, pWh, pQ, pK, pV);

    dim3 fgrid(16, 64);         // S/128 q-blocks, B*H
    flash_attn<<<fgrid, 256, FLASH_SMEM>>>();

    dim3 o_grid(16, 64, 1);
    gemm_nt<0><<<o_grid, 256, GEMM_SMEM>>>(pA, pWh + 3 * WSZ, out, nullptr, nullptr);
}